// round 9
// baseline (speedup 1.0000x reference)
#include <cuda_runtime.h>

typedef unsigned long long ull;

__device__ __forceinline__ ull fma2(ull a, ull b, ull c) {
    ull d;
    asm("fma.rn.f32x2 %0, %1, %2, %3;" : "=l"(d) : "l"(a), "l"(b), "l"(c));
    return d;
}
__device__ __forceinline__ ull pk2(float lo, float hi) {
    ull r;
    asm("mov.b64 %0, {%1, %2};" : "=l"(r) : "f"(lo), "f"(hi));
    return r;
}
__device__ __forceinline__ void unpk(ull v, float& lo, float& hi) {
    asm("mov.b64 {%0, %1}, %2;" : "=f"(lo), "=f"(hi) : "l"(v));
}

#define NWARP 8
#define BPW 2
#define THREADS 256

// dynamic smem layout:
//   [0, 32768)        : W2dup  — 64x64 ull, each = {w,w}  (16B-aligned rows, 512B each)
//   then floats F[]:
//     ctxW_s  2880 (45x64, col 63 zero-padded)
//     gcnW_s  49
//     gcnb_s  7
//     ctxb_s  63
//     W1_s    128
//     b1_s    64
//     W3_s    128
//     b3_s    2      (running float total 3321 -> pad to 3322)
//   b2dup 64 ull (512 B)
//   per-warp staging: 8 * 176 floats (xs 64 | cs 48 | adjf 48 | ds 16)
#define SMEM_BYTES (32768 + 3322*4 + 512 + 8*176*4)

__device__ __forceinline__ float zcalc(int hw, const float* __restrict__ xs,
                                       const float* __restrict__ af,
                                       const float* __restrict__ ds,
                                       const float* __restrict__ gw,
                                       const float* __restrict__ gb) {
    int n = hw / 7;
    int f = hw - n * 7;
    // triu index: idx(n,j) = 9n - n(n-1)/2 + (j-n) = rs + j
    int rs = 9 * n - (n * (n - 1)) / 2 - n;
    float dn = ds[n];
    float acc = gb[f];
    for (int j = n; j < 9; ++j) {
        float y = 0.f;
#pragma unroll
        for (int k = 0; k < 7; ++k)
            y = fmaf(xs[j * 7 + k], gw[k * 7 + f], y);
        float a = (j == n) ? 1.f : af[rs + j];
        acc = fmaf(dn * ds[j] * a, y, acc);
    }
    return acc;
}

__global__ __launch_bounds__(THREADS, 1)
void arnet_kernel(const float* __restrict__ x, const int* __restrict__ adj,
                  const float* __restrict__ ctx,
                  const float* __restrict__ gcn_W, const float* __restrict__ gcn_b,
                  const float* __restrict__ ctx_W, const float* __restrict__ ctx_b,
                  const float* __restrict__ W1, const float* __restrict__ b1,
                  const float* __restrict__ W2, const float* __restrict__ b2,
                  const float* __restrict__ W3, const float* __restrict__ b3,
                  float* __restrict__ out, int Btotal) {
    extern __shared__ char smem_raw[];
    ull* W2d = (ull*)smem_raw;
    float* F = (float*)(smem_raw + 32768);
    float* ctxW_s = F;                  // 2880
    float* gcnW_s = ctxW_s + 2880;      // 49
    float* gcnb_s = gcnW_s + 49;        // 7
    float* ctxb_s = gcnb_s + 7;         // 63
    float* W1_s   = ctxb_s + 63;        // 128
    float* b1_s   = W1_s + 128;         // 64
    float* W3_s   = b1_s + 64;          // 128
    float* b3_s   = W3_s + 128;         // 2
    ull*   b2d    = (ull*)(F + 3322);   // 64 ull
    float* stage  = (float*)(b2d + 64);

    int tid = threadIdx.x;

    // ---- cooperative weight preload ----
    for (int i = tid; i < 4096; i += THREADS) {
        float w = W2[i];
        W2d[i] = pk2(w, w);
    }
    for (int i = tid; i < 45 * 64; i += THREADS) {
        int k = i >> 6, hw = i & 63;
        ctxW_s[i] = (hw < 63) ? ctx_W[k * 63 + hw] : 0.f;
    }
    if (tid < 49)  gcnW_s[tid] = gcn_W[tid];
    if (tid < 7)   gcnb_s[tid] = gcn_b[tid];
    if (tid < 63)  ctxb_s[tid] = ctx_b[tid];
    if (tid < 128) W1_s[tid] = W1[tid];
    if (tid < 64) {
        b1_s[tid] = b1[tid];
        float v = b2[tid];
        b2d[tid] = pk2(v, v);
    }
    if (tid < 128) W3_s[tid] = W3[tid];
    if (tid < 2)   b3_s[tid] = b3[tid];
    __syncthreads();

    int warp = tid >> 5;
    int lane = tid & 31;
    float* xs = stage + warp * 176;
    float* cs = xs + 64;
    float* af = cs + 48;
    float* ds = af + 48;

    int hw0 = 2 * lane;
    int hw1 = hw0 + 1;          // hw1 == 63 on lane 31 -> padded, not stored
    bool has1 = (hw1 < 63);

    for (int it = 0; it < BPW; ++it) {
        int b = (blockIdx.x * NWARP + warp) * BPW + it;
        if (b >= Btotal) break;

        // ---- stage this batch (warp-local); strided: 63/45 exceed warp width ----
        for (int i = lane; i < 63; i += 32) xs[i] = x[b * 63 + i];
        for (int i = lane; i < 45; i += 32) {
            cs[i] = ctx[b * 45 + i];
            af[i] = (adj[b * 45 + i] > 0) ? 1.f : 0.f;
        }
        __syncwarp();
        if (lane < 9) {
            int rstart = 9 * lane - (lane * (lane - 1)) / 2;
            float deg = 1.f;
            for (int j = lane + 1; j < 9; ++j)
                deg += af[rstart + (j - lane)];
            ds[lane] = rsqrtf(deg);
        }
        __syncwarp();

        // ---- context branch: c = relu(cs @ ctxW + ctxb), packed over hw pair ----
        ull cacc = pk2(ctxb_s[hw0], has1 ? ctxb_s[hw1] : 0.f);
#pragma unroll
        for (int k = 0; k < 45; ++k) {
            float cv = cs[k];
            ull wv = *(const ull*)(ctxW_s + k * 64 + hw0);   // 8B-aligned (hw0 even)
            cacc = fma2(pk2(cv, cv), wv, cacc);
        }
        float c0, c1;
        unpk(cacc, c0, c1);
        c0 = fmaxf(c0, 0.f);
        c1 = has1 ? fmaxf(c1, 0.f) : 0.f;

        // ---- GCN branch ----
        float z0 = zcalc(hw0, xs, af, ds, gcnW_s, gcnb_s);
        float z1 = has1 ? zcalc(hw1, xs, af, ds, gcnW_s, gcnb_s) : 0.f;

        // ---- layer 1: h1[o] = relu(W1[o,0]*z + W1[o,1]*c + b1[o]) ----
        ull h1p[64];
#pragma unroll
        for (int cc = 0; cc < 64; ++cc) {
            float w0 = W1_s[cc * 2], w1 = W1_s[cc * 2 + 1], bb = b1_s[cc];
            float a0 = fmaxf(fmaf(w0, z0, fmaf(w1, c0, bb)), 0.f);
            float a1 = fmaxf(fmaf(w0, z1, fmaf(w1, c1, bb)), 0.f);
            h1p[cc] = pk2(a0, a1);
        }

        // ---- layer 2 (dominant) + layer 3 epilogue fused ----
        // LDS.128-vectorized: each ulonglong2 load brings 2 duplicated weight
        // pairs -> 4 LDS.128 : 8 FFMA2 per q-step (was 1:1 with LDS.64).
        float r00 = b3_s[0], r01 = b3_s[0], r10 = b3_s[1], r11 = b3_s[1];
        for (int o = 0; o < 64; o += 4) {
            ull a0 = b2d[o], a1 = b2d[o + 1], a2 = b2d[o + 2], a3 = b2d[o + 3];
            const ulonglong2* wp = (const ulonglong2*)(W2d + o * 64); // row stride = 32 ull2
#pragma unroll
            for (int q = 0; q < 32; ++q) {
                ull ha = h1p[2 * q], hb = h1p[2 * q + 1];
                ulonglong2 w0 = wp[q];
                ulonglong2 w1 = wp[32 + q];
                ulonglong2 w2 = wp[64 + q];
                ulonglong2 w3 = wp[96 + q];
                a0 = fma2(hb, w0.y, fma2(ha, w0.x, a0));
                a1 = fma2(hb, w1.y, fma2(ha, w1.x, a1));
                a2 = fma2(hb, w2.y, fma2(ha, w2.x, a2));
                a3 = fma2(hb, w3.y, fma2(ha, w3.x, a3));
            }
            float lo, hi, w3a, w3b;
            unpk(a0, lo, hi); lo = fmaxf(lo, 0.f); hi = fmaxf(hi, 0.f);
            w3a = W3_s[o];     w3b = W3_s[64 + o];
            r00 = fmaf(w3a, lo, r00); r01 = fmaf(w3a, hi, r01);
            r10 = fmaf(w3b, lo, r10); r11 = fmaf(w3b, hi, r11);

            unpk(a1, lo, hi); lo = fmaxf(lo, 0.f); hi = fmaxf(hi, 0.f);
            w3a = W3_s[o + 1]; w3b = W3_s[64 + o + 1];
            r00 = fmaf(w3a, lo, r00); r01 = fmaf(w3a, hi, r01);
            r10 = fmaf(w3b, lo, r10); r11 = fmaf(w3b, hi, r11);

            unpk(a2, lo, hi); lo = fmaxf(lo, 0.f); hi = fmaxf(hi, 0.f);
            w3a = W3_s[o + 2]; w3b = W3_s[64 + o + 2];
            r00 = fmaf(w3a, lo, r00); r01 = fmaf(w3a, hi, r01);
            r10 = fmaf(w3b, lo, r10); r11 = fmaf(w3b, hi, r11);

            unpk(a3, lo, hi); lo = fmaxf(lo, 0.f); hi = fmaxf(hi, 0.f);
            w3a = W3_s[o + 3]; w3b = W3_s[64 + o + 3];
            r00 = fmaf(w3a, lo, r00); r01 = fmaf(w3a, hi, r01);
            r10 = fmaf(w3b, lo, r10); r11 = fmaf(w3b, hi, r11);
        }

        // ---- store: out[b, 0, hw] and out[b, 1, hw] ----
        float* ob = out + (size_t)b * 126;
        ob[hw0] = r00;
        ob[63 + hw0] = r10;
        if (has1) {
            ob[hw1] = r01;
            ob[63 + hw1] = r11;
        }

        __syncwarp();   // order iteration it's staged-data reads before it+1's writes
    }
}

extern "C" void kernel_launch(void* const* d_in, const int* in_sizes, int n_in,
                              void* d_out, int out_size) {
    const float* x     = (const float*)d_in[0];
    const int*   adj   = (const int*)d_in[1];
    const float* ctx   = (const float*)d_in[2];
    const float* gcn_W = (const float*)d_in[3];
    const float* gcn_b = (const float*)d_in[4];
    const float* ctx_W = (const float*)d_in[5];
    const float* ctx_b = (const float*)d_in[6];
    const float* W1    = (const float*)d_in[7];
    const float* b1    = (const float*)d_in[8];
    const float* W2    = (const float*)d_in[9];
    const float* b2    = (const float*)d_in[10];
    const float* W3    = (const float*)d_in[11];
    const float* b3    = (const float*)d_in[12];
    float* out = (float*)d_out;

    int B = in_sizes[1] / 45;   // adj is (B, 45)
    int blocks = (B + NWARP * BPW - 1) / (NWARP * BPW);

    cudaFuncSetAttribute(arnet_kernel,
                         cudaFuncAttributeMaxDynamicSharedMemorySize, SMEM_BYTES);
    arnet_kernel<<<blocks, THREADS, SMEM_BYTES>>>(
        x, adj, ctx, gcn_W, gcn_b, ctx_W, ctx_b,
        W1, b1, W2, b2, W3, b3, out, B);
}

// round 14
// speedup vs baseline: 1.8044x; 1.8044x over previous
#include <cuda_runtime.h>
#include <cuda_bf16.h>
#include <stdint.h>

// ---------------- warp-level MMA helpers (sm_80+ ISA, safe on sm_103 base target) ----
__device__ __forceinline__ uint32_t smem_u32(const void* p) {
    uint32_t a;
    asm("{ .reg .u64 t; cvta.to.shared.u64 t, %1; cvt.u32.u64 %0, t; }" : "=r"(a) : "l"(p));
    return a;
}
__device__ __forceinline__ void ldsm_x4(uint32_t* r, uint32_t addr) {
    asm volatile("ldmatrix.sync.aligned.m8n8.x4.shared.b16 {%0,%1,%2,%3}, [%4];"
                 : "=r"(r[0]), "=r"(r[1]), "=r"(r[2]), "=r"(r[3]) : "r"(addr));
}
__device__ __forceinline__ void ldsm_x2(uint32_t* r, uint32_t addr) {
    asm volatile("ldmatrix.sync.aligned.m8n8.x2.shared.b16 {%0,%1}, [%2];"
                 : "=r"(r[0]), "=r"(r[1]) : "r"(addr));
}
__device__ __forceinline__ void mma_bf16(float* c, const uint32_t* a, const uint32_t* b) {
    asm volatile("mma.sync.aligned.m16n8k16.row.col.f32.bf16.bf16.f32 "
                 "{%0,%1,%2,%3}, {%4,%5,%6,%7}, {%8,%9}, {%0,%1,%2,%3};"
                 : "+f"(c[0]), "+f"(c[1]), "+f"(c[2]), "+f"(c[3])
                 : "r"(a[0]), "r"(a[1]), "r"(a[2]), "r"(a[3]), "r"(b[0]), "r"(b[1]));
}

// ---------------- smem layout (bytes) ----------------
// A tiles: 128 rows x 128B (64 bf16/row), XOR-swizzled 16B chunks: chunk ^ (row&7)
#define OFF_AHI   0        // 16384
#define OFF_ALO   16384    // 16384
#define OFF_BHI   32768    // 64 rows x 128B = 8192
#define OFF_BLO   40960    // 8192
#define OFF_CTXW  49152    // 45*64 f32 = 11520
#define OFF_EPI   60672    // 64 float4 {W3[0][c], W3[1][c], b2[c], 0} = 1024
#define OFF_W1P   61696    // 128 f32 (W1 pairs) = 512
#define OFF_B1    62208    // 64 f32 = 256
#define OFF_GCNW  62464    // 49 f32 (pad 208)
#define OFF_GCNB  62672    // 7 f32 (pad 32)
#define OFF_CTXB  62704    // 63 f32 (pad 256)
#define OFF_XS    62960    // 126 f32 (pad 512)
#define OFF_CS    63472    // 90 f32 (pad 368)
#define OFF_AF    63840    // 90 f32 (pad 368)
#define OFF_DS    64208    // 18 f32 (pad 80)
#define SMEM_BYTES 64512

__device__ __forceinline__ uint32_t aswz(int row, int chunk) {
    // byte offset of 16B chunk `chunk` in row `row` of a 128B-row tile
    return (uint32_t)(row * 128 + ((chunk ^ (row & 7)) << 4));
}

__device__ __forceinline__ float zcalc(int hw, const float* __restrict__ xs,
                                       const float* __restrict__ af,
                                       const float* __restrict__ ds,
                                       const float* __restrict__ gw,
                                       const float* __restrict__ gb) {
    int n = hw / 7;
    int f = hw - n * 7;
    int rs = 9 * n - (n * (n - 1)) / 2 - n;   // af[rs + j] = triu(n, j), j > n
    float dn = ds[n];
    float acc = gb[f];
    for (int j = n; j < 9; ++j) {
        float y = 0.f;
#pragma unroll
        for (int k = 0; k < 7; ++k)
            y = fmaf(xs[j * 7 + k], gw[k * 7 + f], y);
        float a = (j == n) ? 1.f : af[rs + j];
        acc = fmaf(dn * ds[j] * a, y, acc);
    }
    return acc;
}

__global__ __launch_bounds__(128, 3)
void arnet_hmma_kernel(const float* __restrict__ x, const int* __restrict__ adj,
                       const float* __restrict__ ctx,
                       const float* __restrict__ gcn_W, const float* __restrict__ gcn_b,
                       const float* __restrict__ ctx_W, const float* __restrict__ ctx_b,
                       const float* __restrict__ W1, const float* __restrict__ b1,
                       const float* __restrict__ W2, const float* __restrict__ b2,
                       const float* __restrict__ W3, const float* __restrict__ b3,
                       float* __restrict__ out, int Btotal) {
    extern __shared__ char sm[];
    uint32_t sbase = smem_u32(sm);
    int tid = threadIdx.x;
    int lane = tid & 31;
    int warp = tid >> 5;

    float*  ctxW_s = (float*)(sm + OFF_CTXW);
    float4* epi    = (float4*)(sm + OFF_EPI);
    float*  W1p    = (float*)(sm + OFF_W1P);
    float*  b1_s   = (float*)(sm + OFF_B1);
    float*  gcnW   = (float*)(sm + OFF_GCNW);
    float*  gcnb   = (float*)(sm + OFF_GCNB);
    float*  ctxb   = (float*)(sm + OFF_CTXB);
    float*  xs2    = (float*)(sm + OFF_XS);
    float*  cs2    = (float*)(sm + OFF_CS);
    float*  af2    = (float*)(sm + OFF_AF);
    float*  ds2    = (float*)(sm + OFF_DS);

    int b0 = blockIdx.x * 2;
    int nv = Btotal - b0; if (nv > 2) nv = 2;
    int nrows = 63 * nv;

    // ---- W2 -> bf16 hi/lo swizzled B tiles (row n = output o, 64 bf16 = 128B) ----
    for (int i = tid; i < 4096; i += 128) {
        int n = i >> 6, k = i & 63;
        float w = W2[i];
        __nv_bfloat16 hi = __float2bfloat16_rn(w);
        __nv_bfloat16 lo = __float2bfloat16_rn(w - __bfloat162float(hi));
        uint32_t off = aswz(n, k >> 3) + ((k & 7) << 1);
        *(__nv_bfloat16*)(sm + OFF_BHI + off) = hi;
        *(__nv_bfloat16*)(sm + OFF_BLO + off) = lo;
    }
    for (int i = tid; i < 45 * 64; i += 128) {
        int k = i >> 6, c = i & 63;
        ctxW_s[i] = (c < 63) ? ctx_W[k * 63 + c] : 0.f;
    }
    if (tid < 64) {
        W1p[tid * 2]     = W1[tid * 2];
        W1p[tid * 2 + 1] = W1[tid * 2 + 1];
        b1_s[tid] = b1[tid];
        epi[tid] = make_float4(W3[tid], W3[64 + tid], b2[tid], 0.f);
    }
    if (tid < 49) gcnW[tid] = gcn_W[tid];
    if (tid < 7)  gcnb[tid] = gcn_b[tid];
    if (tid < 63) ctxb[tid] = ctx_b[tid];

    // ---- stage inputs for 2 batches ----
    if (tid < 126) { if (tid < 63 * nv) xs2[tid] = x[(size_t)b0 * 63 + tid]; }
    if (tid < 90) {
        if (tid < 45 * nv) {
            cs2[tid] = ctx[(size_t)b0 * 45 + tid];
            af2[tid] = (adj[(size_t)b0 * 45 + tid] > 0) ? 1.f : 0.f;
        } else { cs2[tid] = 0.f; af2[tid] = 0.f; }
    }
    __syncthreads();

    if (tid < 18) {
        int bl = tid / 9, n = tid - bl * 9;
        const float* af = af2 + bl * 45;
        int rstart = 9 * n - (n * (n - 1)) / 2;
        float deg = 1.f;
        for (int j = n + 1; j < 9; ++j) deg += af[rstart + (j - n)];
        ds2[tid] = rsqrtf(deg);
    }
    __syncthreads();

    // ---- build h1 (one row per thread), hi/lo split, swizzled store ----
    {
        int r = tid;
        if (r < nrows) {
            int bl = (r < 63) ? 0 : 1;
            int hw = r - 63 * bl;
            const float* cs = cs2 + bl * 45;
            float cacc = ctxb[hw];
            for (int k = 0; k < 45; ++k)
                cacc = fmaf(cs[k], ctxW_s[k * 64 + hw], cacc);
            float cx = fmaxf(cacc, 0.f);
            float z = zcalc(hw, xs2 + bl * 63, af2 + bl * 45, ds2 + bl * 9, gcnW, gcnb);
#pragma unroll 4
            for (int c = 0; c < 64; c += 2) {
                float v0 = fmaxf(fmaf(W1p[c * 2],     z, fmaf(W1p[c * 2 + 1], cx, b1_s[c])),     0.f);
                float v1 = fmaxf(fmaf(W1p[c * 2 + 2], z, fmaf(W1p[c * 2 + 3], cx, b1_s[c + 1])), 0.f);
                __nv_bfloat16 h0 = __float2bfloat16_rn(v0);
                __nv_bfloat16 h1 = __float2bfloat16_rn(v1);
                __nv_bfloat16 l0 = __float2bfloat16_rn(v0 - __bfloat162float(h0));
                __nv_bfloat16 l1 = __float2bfloat16_rn(v1 - __bfloat162float(h1));
                uint32_t ph = (uint32_t)__bfloat16_as_ushort(h0) | ((uint32_t)__bfloat16_as_ushort(h1) << 16);
                uint32_t pl = (uint32_t)__bfloat16_as_ushort(l0) | ((uint32_t)__bfloat16_as_ushort(l1) << 16);
                uint32_t off = aswz(r, c >> 3) + ((2 * c) & 15);
                *(uint32_t*)(sm + OFF_AHI + off) = ph;
                *(uint32_t*)(sm + OFF_ALO + off) = pl;
            }
        } else {
#pragma unroll 4
            for (int c = 0; c < 64; c += 2) {
                uint32_t off = aswz(r, c >> 3) + ((2 * c) & 15);
                *(uint32_t*)(sm + OFF_AHI + off) = 0u;
                *(uint32_t*)(sm + OFF_ALO + off) = 0u;
            }
        }
    }
    __syncthreads();

    // ---- warp GEMM: warp owns rows [32*warp, 32*warp+32); D = AhiBhi + AloBhi + AhiBlo ----
    int rowbase = warp * 32;
    float acc[2][8][4];
#pragma unroll
    for (int m = 0; m < 2; ++m)
#pragma unroll
        for (int n = 0; n < 8; ++n)
#pragma unroll
            for (int j = 0; j < 4; ++j) acc[m][n][j] = 0.f;

#pragma unroll
    for (int ks = 0; ks < 4; ++ks) {
        uint32_t ah[2][4], al[2][4];
#pragma unroll
        for (int m = 0; m < 2; ++m) {
            int row = rowbase + m * 16 + (lane & 7) + ((lane >> 3) & 1) * 8;
            int chunk = ks * 2 + ((lane >> 4) & 1);
            uint32_t aoff = aswz(row, chunk);
            ldsm_x4(ah[m], sbase + OFF_AHI + aoff);
            ldsm_x4(al[m], sbase + OFF_ALO + aoff);
        }
#pragma unroll
        for (int n = 0; n < 8; ++n) {
            int nrow = n * 8 + (lane & 7);
            int bch = ks * 2 + ((lane >> 3) & 1);
            uint32_t boff = aswz(nrow, bch);
            uint32_t bh[2], bl_[2];
            ldsm_x2(bh,  sbase + OFF_BHI + boff);
            ldsm_x2(bl_, sbase + OFF_BLO + boff);
#pragma unroll
            for (int m = 0; m < 2; ++m) {
                mma_bf16(acc[m][n], ah[m], bh);
                mma_bf16(acc[m][n], al[m], bh);
                mma_bf16(acc[m][n], ah[m], bl_);
            }
        }
    }

    // ---- epilogue: +b2, relu, x W3, quad-reduce, store ----
    float bb0 = b3[0], bb1 = b3[1];
#pragma unroll
    for (int m = 0; m < 2; ++m) {
#pragma unroll
        for (int rr = 0; rr < 2; ++rr) {
            float o0 = 0.f, o1 = 0.f;
#pragma unroll
            for (int n = 0; n < 8; ++n) {
#pragma unroll
                for (int j = 0; j < 2; ++j) {
                    int col = n * 8 + 2 * (lane & 3) + j;
                    float4 e = epi[col];
                    float h = fmaxf(acc[m][n][rr * 2 + j] + e.z, 0.f);
                    o0 = fmaf(e.x, h, o0);
                    o1 = fmaf(e.y, h, o1);
                }
            }
            o0 += __shfl_xor_sync(0xffffffffu, o0, 1);
            o0 += __shfl_xor_sync(0xffffffffu, o0, 2);
            o1 += __shfl_xor_sync(0xffffffffu, o1, 1);
            o1 += __shfl_xor_sync(0xffffffffu, o1, 2);
            int gr = rowbase + m * 16 + (lane >> 2) + rr * 8;
            if ((lane & 3) == 0 && gr < nrows) {
                int bl = (gr >= 63) ? 1 : 0;
                int hw = gr - 63 * bl;
                float* ob = out + (size_t)(b0 + bl) * 126;
                ob[hw]      = o0 + bb0;
                ob[63 + hw] = o1 + bb1;
            }
        }
    }
}

extern "C" void kernel_launch(void* const* d_in, const int* in_sizes, int n_in,
                              void* d_out, int out_size) {
    const float* x     = (const float*)d_in[0];
    const int*   adj   = (const int*)d_in[1];
    const float* ctx   = (const float*)d_in[2];
    const float* gcn_W = (const float*)d_in[3];
    const float* gcn_b = (const float*)d_in[4];
    const float* ctx_W = (const float*)d_in[5];
    const float* ctx_b = (const float*)d_in[6];
    const float* W1    = (const float*)d_in[7];
    const float* b1    = (const float*)d_in[8];
    const float* W2    = (const float*)d_in[9];
    const float* b2    = (const float*)d_in[10];
    const float* W3    = (const float*)d_in[11];
    const float* b3    = (const float*)d_in[12];
    float* out = (float*)d_out;

    int B = in_sizes[1] / 45;   // adj is (B, 45)
    int blocks = (B + 1) / 2;

    cudaFuncSetAttribute(arnet_hmma_kernel,
                         cudaFuncAttributeMaxDynamicSharedMemorySize, SMEM_BYTES);
    arnet_hmma_kernel<<<blocks, 128, SMEM_BYTES>>>(
        x, adj, ctx, gcn_W, gcn_b, ctx_W, ctx_b,
        W1, b1, W2, b2, W3, b3, out, B);
}

// round 17
// speedup vs baseline: 2.4088x; 1.3350x over previous
#include <cuda_runtime.h>
#include <cuda_bf16.h>
#include <stdint.h>

// ---------------- device-global preprocessed weights ----------------
__device__ uint32_t gW2hi[2048];   // 64x64 bf16, swizzled tile layout (8KB)
__device__ uint32_t gW2lo[2048];
__device__ float    gCtxW[2880];   // [45][64], col 63 zero-padded
__device__ float4   gEpi[64];      // {W3[0][c], W3[1][c], b2[c], 0}

// ---------------- PTX helpers (sm_80+ ISA, safe on sm_103 base target) ----
__device__ __forceinline__ uint32_t smem_u32(const void* p) {
    uint32_t a;
    asm("{ .reg .u64 t; cvta.to.shared.u64 t, %1; cvt.u32.u64 %0, t; }" : "=r"(a) : "l"(p));
    return a;
}
__device__ __forceinline__ void ldsm_x4(uint32_t* r, uint32_t addr) {
    asm volatile("ldmatrix.sync.aligned.m8n8.x4.shared.b16 {%0,%1,%2,%3}, [%4];"
                 : "=r"(r[0]), "=r"(r[1]), "=r"(r[2]), "=r"(r[3]) : "r"(addr));
}
__device__ __forceinline__ void mma_bf16(float* c, const uint32_t* a, const uint32_t* b) {
    asm volatile("mma.sync.aligned.m16n8k16.row.col.f32.bf16.bf16.f32 "
                 "{%0,%1,%2,%3}, {%4,%5,%6,%7}, {%8,%9}, {%0,%1,%2,%3};"
                 : "+f"(c[0]), "+f"(c[1]), "+f"(c[2]), "+f"(c[3])
                 : "r"(a[0]), "r"(a[1]), "r"(a[2]), "r"(a[3]), "r"(b[0]), "r"(b[1]));
}
__device__ __forceinline__ uint32_t prmt7632(uint32_t a, uint32_t b) {
    uint32_t r; asm("prmt.b32 %0, %1, %2, 0x7632;" : "=r"(r) : "r"(a), "r"(b)); return r;
}
// d.hi16 = bf16(vhi), d.lo16 = bf16(vlo)
__device__ __forceinline__ uint32_t cvt_bf16x2(float vhi, float vlo) {
    uint32_t r; asm("cvt.rn.bf16x2.f32 %0, %1, %2;" : "=r"(r) : "f"(vhi), "f"(vlo)); return r;
}
__device__ __forceinline__ uint32_t aswz(int row, int chunk) {
    return (uint32_t)(row * 128 + ((chunk ^ (row & 7)) << 4));
}

// ---------------- smem layout (bytes) ----------------
#define OFF_AHI   0        // 128 rows x 128B
#define OFF_ALO   16384
#define OFF_BHI   32768    // 64 rows x 128B
#define OFF_BLO   40960
#define OFF_CTXW  49152    // 11520
#define OFF_EPI   60672    // 1024
#define OFF_W1P   61696    // 512
#define OFF_B1    62208    // 256
#define OFF_GCNW  62464    // 208
#define OFF_GCNB  62672    // 32
#define OFF_CTXB  62704    // 256
#define OFF_XS    62960    // 8*63 f = 2016
#define OFF_CS    64976    // 8*45 f = 1440
#define OFF_AF    66416    // 1440
#define OFF_DS    67856    // 8*9 f = 288 -> 68144
#define SMEM_BYTES 68160

#define BPC 8      // batches per CTA
#define NTILE 4    // 128-row GEMM tiles per CTA (2 batches each)

// ---------------- prep kernel: convert/pack weights once ----------------
__global__ void prep_kernel(const float* __restrict__ W2, const float* __restrict__ ctx_W,
                            const float* __restrict__ W3, const float* __restrict__ b2) {
    int g = blockIdx.x * 256 + threadIdx.x;      // grid 8 x 256 = 2048
    for (int i = g; i < 4096; i += 2048) {
        int n = i >> 6, k = i & 63;
        float w = W2[i];
        __nv_bfloat16 hi = __float2bfloat16_rn(w);
        __nv_bfloat16 lo = __float2bfloat16_rn(w - __bfloat162float(hi));
        uint32_t off = aswz(n, k >> 3) + ((k & 7) << 1);
        *(__nv_bfloat16*)((char*)gW2hi + off) = hi;
        *(__nv_bfloat16*)((char*)gW2lo + off) = lo;
    }
    for (int i = g; i < 2880; i += 2048) {
        int k = i >> 6, c = i & 63;
        gCtxW[i] = (c < 63) ? ctx_W[k * 63 + c] : 0.f;
    }
    if (g < 64) gEpi[g] = make_float4(W3[g], W3[64 + g], b2[g], 0.f);
}

__device__ __forceinline__ float zcalc(int hw, const float* __restrict__ xs,
                                       const float* __restrict__ af,
                                       const float* __restrict__ ds,
                                       const float* __restrict__ gw,
                                       const float* __restrict__ gb) {
    int n = hw / 7;
    int f = hw - n * 7;
    int rs = 9 * n - (n * (n - 1)) / 2 - n;   // af[rs + j] = triu(n, j), j > n
    float dn = ds[n];
    float acc = gb[f];
    for (int j = n; j < 9; ++j) {
        float y = 0.f;
#pragma unroll
        for (int k = 0; k < 7; ++k)
            y = fmaf(xs[j * 7 + k], gw[k * 7 + f], y);
        float a = (j == n) ? 1.f : af[rs + j];
        acc = fmaf(dn * ds[j] * a, y, acc);
    }
    return acc;
}

__global__ __launch_bounds__(128, 3)
void arnet_hmma_kernel(const float* __restrict__ x, const int* __restrict__ adj,
                       const float* __restrict__ ctx,
                       const float* __restrict__ gcn_W, const float* __restrict__ gcn_b,
                       const float* __restrict__ ctx_b,
                       const float* __restrict__ W1, const float* __restrict__ b1,
                       const float* __restrict__ b3,
                       float* __restrict__ out, int Btotal) {
    extern __shared__ char sm[];
    uint32_t sbase = smem_u32(sm);
    int tid = threadIdx.x;
    int lane = tid & 31;
    int warp = tid >> 5;

    float*  ctxW_s = (float*)(sm + OFF_CTXW);
    float4* epi    = (float4*)(sm + OFF_EPI);
    const float4* W1f4 = (const float4*)(sm + OFF_W1P);
    const float2* b1f2 = (const float2*)(sm + OFF_B1);
    float*  gcnW   = (float*)(sm + OFF_GCNW);
    float*  gcnb   = (float*)(sm + OFF_GCNB);
    float*  ctxb   = (float*)(sm + OFF_CTXB);
    float*  xs2    = (float*)(sm + OFF_XS);
    float*  cs2    = (float*)(sm + OFF_CS);
    float*  af2    = (float*)(sm + OFF_AF);
    float*  ds2    = (float*)(sm + OFF_DS);

    int b0 = blockIdx.x * BPC;

    // ---- vectorized weight preload (pre-converted by prep kernel) ----
    {
        const uint4* shi = (const uint4*)gW2hi;
        const uint4* slo = (const uint4*)gW2lo;
        uint4* dhi = (uint4*)(sm + OFF_BHI);
        uint4* dlo = (uint4*)(sm + OFF_BLO);
#pragma unroll
        for (int j = tid; j < 512; j += 128) { dhi[j] = shi[j]; dlo[j] = slo[j]; }
        const uint4* sc = (const uint4*)gCtxW;
        uint4* dc = (uint4*)(sm + OFF_CTXW);
        for (int j = tid; j < 720; j += 128) dc[j] = sc[j];
    }
    if (tid < 64) epi[tid] = gEpi[tid];
    if (tid < 32) ((float4*)(sm + OFF_W1P))[tid] = ((const float4*)W1)[tid];
    if (tid < 64) ((float*)(sm + OFF_B1))[tid] = b1[tid];
    if (tid < 49) gcnW[tid] = gcn_W[tid];
    if (tid < 7)  gcnb[tid] = gcn_b[tid];
    if (tid < 63) ctxb[tid] = ctx_b[tid];

    // ---- stage 8 batches of inputs ----
    {
        int xlim = Btotal * 63, clim = Btotal * 45;
        for (int i = tid; i < 63 * BPC; i += 128) {
            int gi = b0 * 63 + i;
            xs2[i] = (gi < xlim) ? x[gi] : 0.f;
        }
        for (int i = tid; i < 45 * BPC; i += 128) {
            int gi = b0 * 45 + i;
            bool ok = gi < clim;
            cs2[i] = ok ? ctx[gi] : 0.f;
            af2[i] = (ok && adj[gi] > 0) ? 1.f : 0.f;
        }
    }
    __syncthreads();

    if (tid < 9 * BPC) {
        int bl = tid / 9, n = tid - bl * 9;
        const float* af = af2 + bl * 45;
        int rstart = 9 * n - (n * (n - 1)) / 2;
        float deg = 1.f;
        for (int j = n + 1; j < 9; ++j) deg += af[rstart + (j - n)];
        ds2[tid] = rsqrtf(deg);
    }
    __syncthreads();

    float bb0 = b3[0], bb1 = b3[1];
    int rowbase = warp * 32;

    for (int t = 0; t < NTILE; ++t) {
        // ---- build h1 tile (one row per thread), hi/lo split, swizzled store ----
        {
            int r = tid;
            if (r < 126) {
                int bl2 = (r >= 63);
                int bi = 2 * t + bl2;
                int hw = r - 63 * bl2;
                const float* cs = cs2 + bi * 45;
                float cacc = ctxb[hw];
                for (int k = 0; k < 45; ++k)
                    cacc = fmaf(cs[k], ctxW_s[k * 64 + hw], cacc);
                float cx = fmaxf(cacc, 0.f);
                float z = zcalc(hw, xs2 + bi * 63, af2 + bi * 45, ds2 + bi * 9, gcnW, gcnb);
#pragma unroll 8
                for (int c2 = 0; c2 < 32; ++c2) {
                    float4 w = W1f4[c2];
                    float2 bpair = b1f2[c2];
                    float v0 = fmaxf(fmaf(w.x, z, fmaf(w.y, cx, bpair.x)), 0.f);
                    float v1 = fmaxf(fmaf(w.z, z, fmaf(w.w, cx, bpair.y)), 0.f);
                    uint32_t u0 = __float_as_uint(v0), u1 = __float_as_uint(v1);
                    uint32_t ph = prmt7632(u0, u1);                 // {trunc16(v1), trunc16(v0)}
                    float h0f = __uint_as_float(u0 & 0xFFFF0000u);  // exact hi as float
                    float h1f = __uint_as_float(u1 & 0xFFFF0000u);
                    uint32_t pl = cvt_bf16x2(v1 - h1f, v0 - h0f);   // {bf16(lo1), bf16(lo0)}
                    int c = c2 * 2;
                    uint32_t off = aswz(r, c >> 3) + ((2 * c) & 15);
                    *(uint32_t*)(sm + OFF_AHI + off) = ph;
                    *(uint32_t*)(sm + OFF_ALO + off) = pl;
                }
            } else {
#pragma unroll 8
                for (int c2 = 0; c2 < 32; ++c2) {
                    int c = c2 * 2;
                    uint32_t off = aswz(r, c >> 3) + ((2 * c) & 15);
                    *(uint32_t*)(sm + OFF_AHI + off) = 0u;
                    *(uint32_t*)(sm + OFF_ALO + off) = 0u;
                }
            }
        }
        __syncthreads();

        // ---- warp GEMM: D = AhiBhi + AloBhi + AhiBlo ----
        float acc[2][8][4];
#pragma unroll
        for (int m = 0; m < 2; ++m)
#pragma unroll
            for (int n = 0; n < 8; ++n)
#pragma unroll
                for (int j = 0; j < 4; ++j) acc[m][n][j] = 0.f;

#pragma unroll
        for (int ks = 0; ks < 4; ++ks) {
            uint32_t ah[2][4], al[2][4];
            int arow = rowbase + (lane & 7) + ((lane >> 3) & 1) * 8;
            int ach = ks * 2 + ((lane >> 4) & 1);
#pragma unroll
            for (int m = 0; m < 2; ++m) {
                uint32_t aoff = aswz(arow + m * 16, ach);
                ldsm_x4(ah[m], sbase + OFF_AHI + aoff);
                ldsm_x4(al[m], sbase + OFF_ALO + aoff);
            }
#pragma unroll
            for (int np = 0; np < 4; ++np) {
                // paired-n ldsm_x4: lanes 0-15 -> n=2np, lanes 16-31 -> n=2np+1
                int nrow = (2 * np + ((lane >> 4) & 1)) * 8 + (lane & 7);
                int bch = ks * 2 + ((lane >> 3) & 1);
                uint32_t boff = aswz(nrow, bch);
                uint32_t bh[4], bl_[4];
                ldsm_x4(bh,  sbase + OFF_BHI + boff);
                ldsm_x4(bl_, sbase + OFF_BLO + boff);
#pragma unroll
                for (int m = 0; m < 2; ++m) {
                    mma_bf16(acc[m][2 * np],     ah[m], bh);
                    mma_bf16(acc[m][2 * np],     al[m], bh);
                    mma_bf16(acc[m][2 * np],     ah[m], bl_);
                    mma_bf16(acc[m][2 * np + 1], ah[m], bh + 2);
                    mma_bf16(acc[m][2 * np + 1], al[m], bh + 2);
                    mma_bf16(acc[m][2 * np + 1], ah[m], bl_ + 2);
                }
            }
        }

        // ---- epilogue: +b2, relu, x W3, quad-reduce, store ----
#pragma unroll
        for (int m = 0; m < 2; ++m) {
#pragma unroll
            for (int rr = 0; rr < 2; ++rr) {
                float o0 = 0.f, o1 = 0.f;
#pragma unroll
                for (int n = 0; n < 8; ++n) {
#pragma unroll
                    for (int j = 0; j < 2; ++j) {
                        int col = n * 8 + 2 * (lane & 3) + j;
                        float4 e = epi[col];
                        float h = fmaxf(acc[m][n][rr * 2 + j] + e.z, 0.f);
                        o0 = fmaf(e.x, h, o0);
                        o1 = fmaf(e.y, h, o1);
                    }
                }
                o0 += __shfl_xor_sync(0xffffffffu, o0, 1);
                o0 += __shfl_xor_sync(0xffffffffu, o0, 2);
                o1 += __shfl_xor_sync(0xffffffffu, o1, 1);
                o1 += __shfl_xor_sync(0xffffffffu, o1, 2);
                int gr = rowbase + m * 16 + (lane >> 2) + rr * 8;
                if ((lane & 3) == 0 && gr < 126) {
                    int bl2 = (gr >= 63);
                    int bi = b0 + 2 * t + bl2;
                    if (bi < Btotal) {
                        int hw = gr - 63 * bl2;
                        float* ob = out + (size_t)bi * 126;
                        ob[hw]      = o0 + bb0;
                        ob[63 + hw] = o1 + bb1;
                    }
                }
            }
        }
        __syncthreads();   // protect A smem before next tile's h1 store
    }
}

extern "C" void kernel_launch(void* const* d_in, const int* in_sizes, int n_in,
                              void* d_out, int out_size) {
    const float* x     = (const float*)d_in[0];
    const int*   adj   = (const int*)d_in[1];
    const float* ctx   = (const float*)d_in[2];
    const float* gcn_W = (const float*)d_in[3];
    const float* gcn_b = (const float*)d_in[4];
    const float* ctx_W = (const float*)d_in[5];
    const float* ctx_b = (const float*)d_in[6];
    const float* W1    = (const float*)d_in[7];
    const float* b1    = (const float*)d_in[8];
    const float* W2    = (const float*)d_in[9];
    const float* b2    = (const float*)d_in[10];
    const float* W3    = (const float*)d_in[11];
    const float* b3    = (const float*)d_in[12];
    float* out = (float*)d_out;

    int B = in_sizes[1] / 45;   // adj is (B, 45)
    int blocks = (B + BPC - 1) / BPC;

    prep_kernel<<<8, 256>>>(W2, ctx_W, W3, b2);

    cudaFuncSetAttribute(arnet_hmma_kernel,
                         cudaFuncAttributeMaxDynamicSharedMemorySize, SMEM_BYTES);
    arnet_hmma_kernel<<<blocks, 128, SMEM_BYTES>>>(
        x, adj, ctx, gcn_W, gcn_b, ctx_b,
        W1, b1, b3, out, B);
}